// round 15
// baseline (speedup 1.0000x reference)
#include <cuda_runtime.h>
#include <cuda_fp16.h>
#include <math.h>
#include <stdint.h>

#define NB 64
#define TT 256
#define HH 1024
#define G3 3072
#define GRID 144
#define SPLITS 6
#define NTHREADS 512
#define K0 1536
#define K1 2048
#define CH1 32
#define W0_OFF 0
#define W1_OFF 65536
#define B_OFF 163840
#define B_STAGE 8192
#define SMEM_TOTAL 188416

typedef __half h16;

// ---------------- static device scratch ----------------
__device__ float g_c0[NB * HH];
__device__ float g_c1[NB * HH];
__device__ float g_part0[(size_t)SPLITS * NB * G3];
__device__ float g_part1[(size_t)SPLITS * NB * G3];
__device__ unsigned g_count, g_sense;     // full barrier
__device__ unsigned g_count2, g_sense2;   // deferred barrier

__device__ __align__(16) h16 g_h0[NB * HH];
__device__ __align__(16) h16 g_h1[NB * HH];
__device__ __align__(16) h16 g_x[(size_t)NB * TT * 512];
__device__ __align__(16) h16 g_W0[(size_t)G3 * K0];   // [Wx0|Wh0], rows [i|g|o]
__device__ __align__(16) h16 g_W1[(size_t)G3 * K1];   // [Wx1|Wh1]

// ---------------- helpers ----------------
__device__ __forceinline__ float sigmoid_(float x) {
    return __fdividef(1.0f, 1.0f + __expf(-x));
}
__device__ __forceinline__ float tanh_(float x) {
    return 1.0f - __fdividef(2.0f, __expf(2.0f * x) + 1.0f);
}

__device__ __forceinline__ uint32_t smem_u32(const void* p) {
    uint32_t a;
    asm("{ .reg .u64 t; cvta.to.shared.u64 t, %1; cvt.u32.u64 %0, t; }" : "=r"(a) : "l"(p));
    return a;
}
#define SWZ(x) ((x) ^ (((x) >> 3) & 0x70))

__device__ __forceinline__ void cp16(uint32_t dst, const void* src) {
    asm volatile("cp.async.cg.shared.global [%0], [%1], 16;" :: "r"(dst), "l"(src));
}
#define CP_COMMIT() asm volatile("cp.async.commit_group;" ::: "memory")

#define LDSM4(r, addr) \
    asm volatile("ldmatrix.sync.aligned.m8n8.x4.shared.b16 {%0,%1,%2,%3}, [%4];" \
        : "=r"((r)[0]), "=r"((r)[1]), "=r"((r)[2]), "=r"((r)[3]) : "r"(addr))

#define MMA(c, a, b0, b1) \
    asm volatile("mma.sync.aligned.m16n8k16.row.col.f32.f16.f16.f32 " \
        "{%0,%1,%2,%3},{%4,%5,%6,%7},{%8,%9},{%0,%1,%2,%3};" \
        : "+f"((c)[0]), "+f"((c)[1]), "+f"((c)[2]), "+f"((c)[3]) \
        : "r"((a)[0]), "r"((a)[1]), "r"((a)[2]), "r"((a)[3]), "r"(b0), "r"(b1))

// full sense-reversing grid barrier (atomic; R13-proven)
__device__ __forceinline__ void grid_sync(int& sense) {
    sense ^= 1;
    __syncthreads();
    if (threadIdx.x == 0) {
        __threadfence();
        unsigned old = atomicAdd(&g_count, 1u);
        if (old == GRID - 1) {
            g_count = 0;
            asm volatile("st.global.release.gpu.u32 [%0], %1;"
                         :: "l"(&g_sense), "r"((unsigned)sense));
        } else {
            unsigned v;
            do {
                asm volatile("ld.global.acquire.gpu.u32 %0, [%1];"
                             : "=r"(v) : "l"(&g_sense));
            } while (v != (unsigned)sense);
        }
    }
    __syncthreads();
}

// deferred barrier: arrive (non-blocking) / wait (blocking), split in time
__device__ __forceinline__ void dbar_arrive(int& as) {
    as ^= 1;
    __syncthreads();                 // all CTA threads finished pw stores
    if (threadIdx.x == 0) {
        __threadfence();
        unsigned old = atomicAdd(&g_count2, 1u);
        if (old == GRID - 1) {
            g_count2 = 0;
            asm volatile("st.global.release.gpu.u32 [%0], %1;"
                         :: "l"(&g_sense2), "r"((unsigned)as));
        }
    }
}
__device__ __forceinline__ void dbar_wait(int& ws) {
    ws ^= 1;
    if (threadIdx.x == 0) {
        unsigned v;
        do {
            asm volatile("ld.global.acquire.gpu.u32 %0, [%1];"
                         : "=r"(v) : "l"(&g_sense2));
        } while (v != (unsigned)ws);
    }
    __syncthreads();
}

// ---------------- init / convert ----------------
__global__ void init_state() {
    int i = blockIdx.x * blockDim.x + threadIdx.x;
    if (i == 0) { g_count = 0u; g_sense = 0u; g_count2 = 0u; g_sense2 = 0u; }
    if (i < NB * HH) {
        g_c0[i] = 0.f; g_c1[i] = 0.f;
        h16 z = __float2half(0.f);
        g_h0[i] = z; g_h1[i] = z;
    }
}

#define NW0E ((size_t)G3 * K0)
#define NW1E ((size_t)G3 * K1)
#define NXE  ((size_t)NB * TT * 512)

__global__ void convert_all(const float* __restrict__ x,
    const float* __restrict__ Wx0, const float* __restrict__ Wh0,
    const float* __restrict__ Wx1, const float* __restrict__ Wh1)
{
    size_t idx = (size_t)blockIdx.x * 256 + threadIdx.x;
    if (idx < NW0E) {
        int r = (int)(idx / K0), k = (int)(idx % K0);
        int R = r + (r >= HH ? HH : 0);        // packed [i|g|o] -> orig [i,f,g,o]
        float v = (k < 512) ? Wx0[(size_t)R * 512 + k] : Wh0[(size_t)R * HH + (k - 512)];
        g_W0[idx] = __float2half(v);
    } else if (idx < NW0E + NW1E) {
        size_t i2 = idx - NW0E;
        int r = (int)(i2 / K1), k = (int)(i2 % K1);
        int R = r + (r >= HH ? HH : 0);
        float v = (k < HH) ? Wx1[(size_t)R * HH + k] : Wh1[(size_t)R * HH + (k - HH)];
        g_W1[i2] = __float2half(v);
    } else {
        size_t i2 = idx - NW0E - NW1E;
        if (i2 >= NXE) return;
        g_x[i2] = __float2half(x[i2]);
    }
}

// ---------------- smem tile loads (512 threads) ----------------
__device__ __forceinline__ void load_Wslot(uint32_t sbase,
    const h16* __restrict__ W, int k0, int ws, int tid)
{
#pragma unroll
    for (int i = 0; i < 2; i++) {
        int seg = tid + i * NTHREADS;          // 0..1023
        int row = seg >> 3, sc = seg & 7;
        uint32_t so = SWZ((uint32_t)(row * 128 + sc * 16));
        cp16(sbase + so, W + (size_t)row * ws + k0 + sc * 8);
    }
}
__device__ __forceinline__ void load_Bstage(uint32_t sbase,
    const h16* __restrict__ B, int k0, int bs, int tid)
{
    int row = tid >> 3, sc = tid & 7;          // 64 rows x 8 segs = 512
    uint32_t so = SWZ((uint32_t)(row * 128 + sc * 16));
    cp16(sbase + so, B + (size_t)row * bs + k0 + sc * 8);
}

// B source for a global chunk. L0: c<8 -> x(t) (STATIC), else h0. L1: c<16 -> h0, else h1.
template <int LAYER>
__device__ __forceinline__ void getB(int c, int t,
    const h16*& B, int& bk0, int& bs)
{
    if (LAYER == 0) {
        if (c < 8) { B = g_x + (size_t)t * 512; bs = TT * 512; bk0 = c * 64; }
        else       { B = g_h0; bs = HH; bk0 = (c - 8) * 64; }
    } else {
        if (c < 16) { B = g_h0; bs = HH; bk0 = c * 64; }
        else        { B = g_h1; bs = HH; bk0 = (c - 16) * 64; }
    }
}

// ---------------- warp MMA: 16 warps (4M x 4N), 1-term fp16 ----------------
__device__ __forceinline__ void compute_chunk(uint32_t wslot, uint32_t bstage,
    float acc[2][2][4], int lane, int warpM, int warpN)
{
#pragma unroll
    for (int kk = 0; kk < 4; kk++) {
        const int kByte = kk * 32;
        uint32_t ah[2][4];
#pragma unroll
        for (int mt = 0; mt < 2; mt++) {
            int row = warpM * 32 + mt * 16 + (lane & 7) + ((lane >> 3) & 1) * 8;
            int col = kByte + ((lane >> 4) << 4);
            LDSM4(ah[mt], wslot + SWZ((uint32_t)(row * 128 + col)));
        }
        uint32_t bh[4];
        {
            int row = warpN * 16 + (lane & 7) + ((lane >> 4) & 1) * 8;
            int col = kByte + (((lane >> 3) & 1) << 4);
            LDSM4(bh, bstage + SWZ((uint32_t)(row * 128 + col)));
        }
#pragma unroll
        for (int mt = 0; mt < 2; mt++)
#pragma unroll
            for (int nt = 0; nt < 2; nt++)
                MMA(acc[mt][nt], ah[mt], bh[nt * 2], bh[nt * 2 + 1]);
    }
}

// slot -> global chunk. gemm0 is round-robin (every split owns 1-2 static x-chunks).
template <int LAYER>
__device__ __forceinline__ int slot_chunk(int sp, int s) {
    return (LAYER == 0) ? (sp + SPLITS * s) : ((sp * CH1) / SPLITS + s);
}

// run pipeline over local W slots [s_begin, s_end) of one layer
template <int LAYER>
__device__ __forceinline__ void gemm_chunks(uint32_t smem, float acc[2][2][4],
                                            int s_begin, int s_end, int sp, int t)
{
    if (s_begin >= s_end) return;
    const int tid = threadIdx.x;
    const int lane = tid & 31, wid = tid >> 5;
    const int warpM = wid & 3, warpN = wid >> 2;
    const uint32_t wbase = smem + (LAYER == 0 ? W0_OFF : W1_OFF);

    auto ldB = [&](int s) {
        const h16* B; int bk0, bs;
        getB<LAYER>(slot_chunk<LAYER>(sp, s), t, B, bk0, bs);
        load_Bstage(smem + B_OFF + (s % 3) * B_STAGE, B, bk0, bs, tid);
        CP_COMMIT();
    };
    ldB(s_begin);
    if (s_begin + 1 < s_end) ldB(s_begin + 1);
    for (int s = s_begin; s < s_end; s++) {
        if (s + 1 < s_end) { asm volatile("cp.async.wait_group 1;" ::: "memory"); }
        else               { asm volatile("cp.async.wait_group 0;" ::: "memory"); }
        __syncthreads();
        if (s + 2 < s_end) ldB(s + 2);
        compute_chunk(wbase + (uint32_t)s * 16384,
                      smem + B_OFF + (s % 3) * B_STAGE, acc, lane, warpM, warpN);
    }
    __syncthreads();
}

// fused post-wait stream: U0 gemm0 chunks (time t+1, slots nx..) then n1 gemm1
// chunks (time t) in ONE continuous 3-stage pipeline (single fill/drain).
__device__ __forceinline__ void gemm_fused(uint32_t smem,
    float acc0[2][2][4], float acc1[2][2][4], int sp, int t, int nx, int U0, int n1)
{
    const int U = U0 + n1;
    const int tid = threadIdx.x;
    const int lane = tid & 31, wid = tid >> 5;
    const int warpM = wid & 3, warpN = wid >> 2;

    auto ldB = [&](int u) {
        const h16* B; int bk0, bs;
        if (u < U0) getB<0>(slot_chunk<0>(sp, nx + u), t + 1, B, bk0, bs);
        else        getB<1>(slot_chunk<1>(sp, u - U0), t, B, bk0, bs);
        load_Bstage(smem + B_OFF + (u % 3) * B_STAGE, B, bk0, bs, tid);
        CP_COMMIT();
    };
    ldB(0);
    if (U > 1) ldB(1);
    for (int u = 0; u < U; u++) {
        if (u + 1 < U) { asm volatile("cp.async.wait_group 1;" ::: "memory"); }
        else           { asm volatile("cp.async.wait_group 0;" ::: "memory"); }
        __syncthreads();
        if (u + 2 < U) ldB(u + 2);
        uint32_t wslot = (u < U0)
            ? smem + W0_OFF + (uint32_t)(nx + u) * 16384
            : smem + W1_OFF + (uint32_t)(u - U0) * 16384;
        compute_chunk(wslot, smem + B_OFF + (u % 3) * B_STAGE,
                      (u < U0) ? acc0 : acc1, lane, warpM, warpN);
    }
    __syncthreads();
}

__device__ __forceinline__ void store_part(float acc[2][2][4], float* __restrict__ part,
                                           int sp, int col0)
{
    const int lane = threadIdx.x & 31, wid = threadIdx.x >> 5;
    const int warpM = wid & 3, warpN = wid >> 2;
    const int g = lane >> 2, tig = lane & 3;
#pragma unroll
    for (int mt = 0; mt < 2; mt++) {
        int colA = col0 + warpM * 32 + mt * 16 + g;
#pragma unroll
        for (int nt = 0; nt < 2; nt++) {
            int b = warpN * 16 + nt * 8 + tig * 2;
            float* p0 = part + ((size_t)sp * NB + b) * G3;
            p0[colA] = acc[mt][nt][0];
            p0[G3 + colA] = acc[mt][nt][1];
            p0[colA + 8] = acc[mt][nt][2];
            p0[G3 + colA + 8] = acc[mt][nt][3];
        }
    }
}

#define ZACC(a) do { \
_Pragma("unroll") for (int _i = 0; _i < 2; _i++) \
_Pragma("unroll") for (int _j = 0; _j < 2; _j++) \
_Pragma("unroll") for (int _k = 0; _k < 4; _k++) (a)[_i][_j][_k] = 0.f; } while (0)

// ---------------- pointwise (one layer, one cell per thread) ----------------
__device__ __forceinline__ void pw_layer(const float* __restrict__ part,
    const float* __restrict__ bias, const float* __restrict__ Wc,
    float* __restrict__ cb, h16* __restrict__ h_buf,
    float* __restrict__ out, int t, bool isL1, int cell)
{
    int b = cell >> 10, j = cell & (HH - 1);
    float si = 0.f, sg = 0.f, so = 0.f;
#pragma unroll
    for (int sp = 0; sp < SPLITS; sp++) {
        const float* p = part + ((size_t)sp * NB + b) * G3 + j;
        si += p[0]; sg += p[HH]; so += p[2 * HH];
    }
    float pi = si + bias[j];
    float pg = sg + bias[2 * HH + j];
    float po = so + bias[3 * HH + j];
    float c = cb[cell];
    float ig = sigmoid_(pi + Wc[j] * c);
    float gg = tanh_(pg);
    float og = sigmoid_(po + Wc[2 * HH + j] * c);
    float cn = gg * (c + ig);      // faithful: forget gate unused
    float hn = og * tanh_(c);      // faithful: uses OLD cell state
    cb[cell] = cn;
    h_buf[cell] = __float2half(hn);
    if (isL1) {
        out[((size_t)b * TT + t) * HH + j] = hn;
        if (t == TT - 1) {
            out[(size_t)NB * TT * HH + cell] = hn;
            out[(size_t)NB * TT * HH + NB * HH + cell] = cn;
        }
    }
}

__global__ __launch_bounds__(NTHREADS, 1) void lstm_persistent(
    const float* __restrict__ b0, const float* __restrict__ b1,
    const float* __restrict__ Wc0, const float* __restrict__ Wc1,
    float* __restrict__ out)
{
    extern __shared__ char smem_raw[];
    uint32_t smem = smem_u32(smem_raw);
    const int ct = blockIdx.x / SPLITS, sp = blockIdx.x % SPLITS;
    const int col0 = ct * 128;
    const int lo1 = (sp * CH1) / SPLITS, hi1 = ((sp + 1) * CH1) / SPLITS;
    const int n1 = hi1 - lo1;
    const int nx = (sp < 2) ? 2 : 1;           // static x slots in gemm0 round-robin
    const int tid = threadIdx.x;
    const int cell = blockIdx.x * NTHREADS + tid;
    const bool hasCell = (cell < NB * HH);

    // one-time: resident W slices (gemm0 slots round-robin: chunk sp + 6*s)
#pragma unroll
    for (int s = 0; s < 4; s++)
        load_Wslot(smem + W0_OFF + s * 16384, g_W0 + (size_t)col0 * K0,
                   (sp + SPLITS * s) * 64, K0, tid);
    for (int s = 0; s < n1; s++)
        load_Wslot(smem + W1_OFF + s * 16384, g_W1 + (size_t)col0 * K1,
                   (lo1 + s) * 64, K1, tid);
    CP_COMMIT();
    asm volatile("cp.async.wait_group 0;" ::: "memory");
    __syncthreads();

    int sense = 0, as = 0, ws = 0;
    // ---- prologue: h0(0) (h0/h1 initial zeros already global-visible)
    {
        float acc[2][2][4]; ZACC(acc);
        gemm_chunks<0>(smem, acc, 0, 4, sp, 0);
        store_part(acc, g_part0, sp, col0);
        grid_sync(sense);
        if (hasCell) pw_layer(g_part0, b0, Wc0, g_c0, g_h0, out, 0, false, cell);
        dbar_arrive(as);
    }

    // ---- steady state: 1 blocking sync + 1 hidden (deferred) sync per step
    for (int t = 0; t < TT; t++) {
        const int U0 = (t + 1 < TT) ? (4 - nx) : 0;
        float acc0[2][2][4];
        if (t + 1 < TT) {                     // gemm0(t+1): x-chunks BEFORE the wait
            ZACC(acc0);
            gemm_chunks<0>(smem, acc0, 0, nx, sp, t + 1);
        }
        dbar_wait(ws);                        // pw(t-1 epoch) globally complete
        {
            float acc1[2][2][4]; ZACC(acc1);
            gemm_fused(smem, acc0, acc1, sp, t, nx, U0, n1);  // one fill/drain
            if (t + 1 < TT) store_part(acc0, g_part0, sp, col0);
            store_part(acc1, g_part1, sp, col0);
        }
        grid_sync(sense);                     // all partials visible
        if (hasCell) {
            pw_layer(g_part1, b1, Wc1, g_c1, g_h1, out, t, true, cell);
            if (t + 1 < TT)
                pw_layer(g_part0, b0, Wc0, g_c0, g_h0, out, t + 1, false, cell);
        }
        dbar_arrive(as);
    }
}

// ---------------- host launch ----------------
extern "C" void kernel_launch(void* const* d_in, const int* in_sizes, int n_in,
                              void* d_out, int out_size) {
    const float* x   = (const float*)d_in[0];
    const float* Wx0 = (const float*)d_in[1];
    const float* Wh0 = (const float*)d_in[2];
    const float* b0  = (const float*)d_in[3];
    const float* Wc0 = (const float*)d_in[4];
    const float* Wx1 = (const float*)d_in[5];
    const float* Wh1 = (const float*)d_in[6];
    const float* b1  = (const float*)d_in[7];
    const float* Wc1 = (const float*)d_in[8];
    float* out = (float*)d_out;

    cudaFuncSetAttribute(lstm_persistent,
                         cudaFuncAttributeMaxDynamicSharedMemorySize, SMEM_TOTAL);

    size_t total_conv = NW0E + NW1E + NXE;
    int conv_blocks = (int)((total_conv + 255) / 256);

    init_state<<<256, 256>>>();
    convert_all<<<conv_blocks, 256>>>(x, Wx0, Wh0, Wx1, Wh1);
    lstm_persistent<<<GRID, NTHREADS, SMEM_TOTAL>>>(b0, b1, Wc0, Wc1, out);
}

// round 16
// speedup vs baseline: 2.6579x; 2.6579x over previous
#include <cuda_runtime.h>
#include <cuda_fp16.h>
#include <math.h>
#include <stdint.h>

#define NB 64
#define TT 256
#define HH 1024
#define G3 3072
#define GRID 144
#define SPLITS 6
#define NTHREADS 512
#define K0 1536
#define K1 2048
#define CH1 32
#define W0_OFF 0
#define W1_OFF 65536
#define B_OFF 163840
#define B_STAGE 8192
#define SMEM_TOTAL 188416

typedef __half h16;

// ---------------- static device scratch ----------------
__device__ float g_c0[NB * HH];
__device__ float g_c1[NB * HH];
__device__ float g_part0[(size_t)SPLITS * NB * G3];
__device__ float g_part1[(size_t)SPLITS * NB * G3];
__device__ unsigned g_count, g_sense;     // full barrier
__device__ unsigned g_count2, g_sense2;   // deferred barrier

__device__ __align__(16) h16 g_h0[NB * HH];
__device__ __align__(16) h16 g_h1[NB * HH];
__device__ __align__(16) h16 g_x[(size_t)NB * TT * 512];
__device__ __align__(16) h16 g_W0[(size_t)G3 * K0];   // [Wx0|Wh0], rows [i|g|o]
__device__ __align__(16) h16 g_W1[(size_t)G3 * K1];   // [Wx1|Wh1]

// ---------------- helpers ----------------
__device__ __forceinline__ float sigmoid_(float x) {
    return __fdividef(1.0f, 1.0f + __expf(-x));
}
__device__ __forceinline__ float tanh_(float x) {
    return 1.0f - __fdividef(2.0f, __expf(2.0f * x) + 1.0f);
}

__device__ __forceinline__ uint32_t smem_u32(const void* p) {
    uint32_t a;
    asm("{ .reg .u64 t; cvta.to.shared.u64 t, %1; cvt.u32.u64 %0, t; }" : "=r"(a) : "l"(p));
    return a;
}
#define SWZ(x) ((x) ^ (((x) >> 3) & 0x70))

__device__ __forceinline__ void cp16(uint32_t dst, const void* src) {
    asm volatile("cp.async.cg.shared.global [%0], [%1], 16;" :: "r"(dst), "l"(src));
}
#define CP_COMMIT() asm volatile("cp.async.commit_group;" ::: "memory")

#define LDSM4(r, addr) \
    asm volatile("ldmatrix.sync.aligned.m8n8.x4.shared.b16 {%0,%1,%2,%3}, [%4];" \
        : "=r"((r)[0]), "=r"((r)[1]), "=r"((r)[2]), "=r"((r)[3]) : "r"(addr))

#define MMA(c, a, b0, b1) \
    asm volatile("mma.sync.aligned.m16n8k16.row.col.f32.f16.f16.f32 " \
        "{%0,%1,%2,%3},{%4,%5,%6,%7},{%8,%9},{%0,%1,%2,%3};" \
        : "+f"((c)[0]), "+f"((c)[1]), "+f"((c)[2]), "+f"((c)[3]) \
        : "r"((a)[0]), "r"((a)[1]), "r"((a)[2]), "r"((a)[3]), "r"(b0), "r"(b1))

// full sense-reversing grid barrier (atomic; R13-proven)
__device__ __forceinline__ void grid_sync(int& sense) {
    sense ^= 1;
    __syncthreads();
    if (threadIdx.x == 0) {
        __threadfence();
        unsigned old = atomicAdd(&g_count, 1u);
        if (old == GRID - 1) {
            g_count = 0;
            asm volatile("st.global.release.gpu.u32 [%0], %1;"
                         :: "l"(&g_sense), "r"((unsigned)sense));
        } else {
            unsigned v;
            do {
                asm volatile("ld.global.acquire.gpu.u32 %0, [%1];"
                             : "=r"(v) : "l"(&g_sense));
            } while (v != (unsigned)sense);
        }
    }
    __syncthreads();
}

// deferred barrier: arrive (non-blocking) / wait (blocking), split in time
__device__ __forceinline__ void dbar_arrive(int& as) {
    as ^= 1;
    __syncthreads();                 // all CTA threads finished pw stores
    if (threadIdx.x == 0) {
        __threadfence();
        unsigned old = atomicAdd(&g_count2, 1u);
        if (old == GRID - 1) {
            g_count2 = 0;
            asm volatile("st.global.release.gpu.u32 [%0], %1;"
                         :: "l"(&g_sense2), "r"((unsigned)as));
        }
    }
}
__device__ __forceinline__ void dbar_wait(int& ws) {
    ws ^= 1;
    if (threadIdx.x == 0) {
        unsigned v;
        do {
            asm volatile("ld.global.acquire.gpu.u32 %0, [%1];"
                         : "=r"(v) : "l"(&g_sense2));
        } while (v != (unsigned)ws);
    }
    __syncthreads();
}

// ---------------- init / convert ----------------
__global__ void init_state() {
    int i = blockIdx.x * blockDim.x + threadIdx.x;
    if (i == 0) { g_count = 0u; g_sense = 0u; g_count2 = 0u; g_sense2 = 0u; }
    if (i < NB * HH) {
        g_c0[i] = 0.f; g_c1[i] = 0.f;
        h16 z = __float2half(0.f);
        g_h0[i] = z; g_h1[i] = z;
    }
}

#define NW0E ((size_t)G3 * K0)
#define NW1E ((size_t)G3 * K1)
#define NXE  ((size_t)NB * TT * 512)

__global__ void convert_all(const float* __restrict__ x,
    const float* __restrict__ Wx0, const float* __restrict__ Wh0,
    const float* __restrict__ Wx1, const float* __restrict__ Wh1)
{
    size_t idx = (size_t)blockIdx.x * 256 + threadIdx.x;
    if (idx < NW0E) {
        int r = (int)(idx / K0), k = (int)(idx % K0);
        int R = r + (r >= HH ? HH : 0);        // packed [i|g|o] -> orig [i,f,g,o]
        float v = (k < 512) ? Wx0[(size_t)R * 512 + k] : Wh0[(size_t)R * HH + (k - 512)];
        g_W0[idx] = __float2half(v);
    } else if (idx < NW0E + NW1E) {
        size_t i2 = idx - NW0E;
        int r = (int)(i2 / K1), k = (int)(i2 % K1);
        int R = r + (r >= HH ? HH : 0);
        float v = (k < HH) ? Wx1[(size_t)R * HH + k] : Wh1[(size_t)R * HH + (k - HH)];
        g_W1[i2] = __float2half(v);
    } else {
        size_t i2 = idx - NW0E - NW1E;
        if (i2 >= NXE) return;
        g_x[i2] = __float2half(x[i2]);
    }
}

// ---------------- smem tile loads (512 threads) ----------------
__device__ __forceinline__ void load_Wslot(uint32_t sbase,
    const h16* __restrict__ W, int k0, int ws, int tid)
{
#pragma unroll
    for (int i = 0; i < 2; i++) {
        int seg = tid + i * NTHREADS;          // 0..1023
        int row = seg >> 3, sc = seg & 7;
        uint32_t so = SWZ((uint32_t)(row * 128 + sc * 16));
        cp16(sbase + so, W + (size_t)row * ws + k0 + sc * 8);
    }
}
__device__ __forceinline__ void load_Bstage(uint32_t sbase,
    const h16* __restrict__ B, int k0, int bs, int tid)
{
    int row = tid >> 3, sc = tid & 7;          // 64 rows x 8 segs = 512
    uint32_t so = SWZ((uint32_t)(row * 128 + sc * 16));
    cp16(sbase + so, B + (size_t)row * bs + k0 + sc * 8);
}

// B source for a global chunk. L0: c<8 -> x(t) (STATIC), else h0. L1: c<16 -> h0, else h1.
template <int LAYER>
__device__ __forceinline__ void getB(int c, int t,
    const h16*& B, int& bk0, int& bs)
{
    if (LAYER == 0) {
        if (c < 8) { B = g_x + (size_t)t * 512; bs = TT * 512; bk0 = c * 64; }
        else       { B = g_h0; bs = HH; bk0 = (c - 8) * 64; }
    } else {
        if (c < 16) { B = g_h0; bs = HH; bk0 = c * 64; }
        else        { B = g_h1; bs = HH; bk0 = (c - 16) * 64; }
    }
}

// ---------------- warp MMA: 16 warps (4M x 4N), 1-term fp16 ----------------
__device__ __forceinline__ void compute_chunk(uint32_t wslot, uint32_t bstage,
    float acc[2][2][4], int lane, int warpM, int warpN)
{
#pragma unroll
    for (int kk = 0; kk < 4; kk++) {
        const int kByte = kk * 32;
        uint32_t ah[2][4];
#pragma unroll
        for (int mt = 0; mt < 2; mt++) {
            int row = warpM * 32 + mt * 16 + (lane & 7) + ((lane >> 3) & 1) * 8;
            int col = kByte + ((lane >> 4) << 4);
            LDSM4(ah[mt], wslot + SWZ((uint32_t)(row * 128 + col)));
        }
        uint32_t bh[4];
        {
            int row = warpN * 16 + (lane & 7) + ((lane >> 4) & 1) * 8;
            int col = kByte + (((lane >> 3) & 1) << 4);
            LDSM4(bh, bstage + SWZ((uint32_t)(row * 128 + col)));
        }
#pragma unroll
        for (int mt = 0; mt < 2; mt++)
#pragma unroll
            for (int nt = 0; nt < 2; nt++)
                MMA(acc[mt][nt], ah[mt], bh[nt * 2], bh[nt * 2 + 1]);
    }
}

// slot -> global chunk. gemm0 is round-robin (every split owns 1-2 static x-chunks).
template <int LAYER>
__device__ __forceinline__ int slot_chunk(int sp, int s) {
    return (LAYER == 0) ? (sp + SPLITS * s) : ((sp * CH1) / SPLITS + s);
}

__device__ __forceinline__ void store_part(float acc[2][2][4], float* __restrict__ part,
                                           int sp, int col0)
{
    const int lane = threadIdx.x & 31, wid = threadIdx.x >> 5;
    const int warpM = wid & 3, warpN = wid >> 2;
    const int g = lane >> 2, tig = lane & 3;
#pragma unroll
    for (int mt = 0; mt < 2; mt++) {
        int colA = col0 + warpM * 32 + mt * 16 + g;
#pragma unroll
        for (int nt = 0; nt < 2; nt++) {
            int b = warpN * 16 + nt * 8 + tig * 2;
            float* p0 = part + ((size_t)sp * NB + b) * G3;
            p0[colA] = acc[mt][nt][0];
            p0[G3 + colA] = acc[mt][nt][1];
            p0[colA + 8] = acc[mt][nt][2];
            p0[G3 + colA + 8] = acc[mt][nt][3];
        }
    }
}

// run pipeline over local W slots [s_begin, s_end) of one layer
template <int LAYER>
__device__ __forceinline__ void gemm_chunks(uint32_t smem, float acc[2][2][4],
                                            int s_begin, int s_end, int sp, int t)
{
    if (s_begin >= s_end) return;
    const int tid = threadIdx.x;
    const int lane = tid & 31, wid = tid >> 5;
    const int warpM = wid & 3, warpN = wid >> 2;
    const uint32_t wbase = smem + (LAYER == 0 ? W0_OFF : W1_OFF);

    auto ldB = [&](int s) {
        const h16* B; int bk0, bs;
        getB<LAYER>(slot_chunk<LAYER>(sp, s), t, B, bk0, bs);
        load_Bstage(smem + B_OFF + (s % 3) * B_STAGE, B, bk0, bs, tid);
        CP_COMMIT();
    };
    ldB(s_begin);
    if (s_begin + 1 < s_end) ldB(s_begin + 1);
    for (int s = s_begin; s < s_end; s++) {
        if (s + 1 < s_end) { asm volatile("cp.async.wait_group 1;" ::: "memory"); }
        else               { asm volatile("cp.async.wait_group 0;" ::: "memory"); }
        __syncthreads();
        if (s + 2 < s_end) ldB(s + 2);
        compute_chunk(wbase + (uint32_t)s * 16384,
                      smem + B_OFF + (s % 3) * B_STAGE, acc, lane, warpM, warpN);
    }
    __syncthreads();
}

// fused post-wait stream: U0 gemm0 chunks (t+1, slots nx..3) then n1 gemm1 chunks (t)
// in ONE 3-stage pipeline. Compute sites are BRANCHED so each acc array stays in
// registers (no dynamic pointer selection -> no local-mem spill). acc0 is stored
// at u == U0-1 so its live range ends before acc1's begins (register overlay).
__device__ __forceinline__ void gemm_fused(uint32_t smem,
    float acc0[2][2][4], float acc1[2][2][4],
    int sp, int col0, int t, int nx, int U0, int n1)
{
    const int U = U0 + n1;
    const int tid = threadIdx.x;
    const int lane = tid & 31, wid = tid >> 5;
    const int warpM = wid & 3, warpN = wid >> 2;

    auto ldB = [&](int u) {
        const h16* B; int bk0, bs;
        if (u < U0) getB<0>(slot_chunk<0>(sp, nx + u), t + 1, B, bk0, bs);
        else        getB<1>(slot_chunk<1>(sp, u - U0), t, B, bk0, bs);
        load_Bstage(smem + B_OFF + (u % 3) * B_STAGE, B, bk0, bs, tid);
        CP_COMMIT();
    };
    ldB(0);
    if (U > 1) ldB(1);
    for (int u = 0; u < U; u++) {
        if (u + 1 < U) { asm volatile("cp.async.wait_group 1;" ::: "memory"); }
        else           { asm volatile("cp.async.wait_group 0;" ::: "memory"); }
        __syncthreads();
        if (u + 2 < U) ldB(u + 2);
        uint32_t bst = smem + B_OFF + (u % 3) * B_STAGE;
        if (u < U0) {
            compute_chunk(smem + W0_OFF + (uint32_t)(nx + u) * 16384, bst,
                          acc0, lane, warpM, warpN);
            if (u == U0 - 1) store_part(acc0, g_part0, sp, col0);  // acc0 dies here
        } else {
            compute_chunk(smem + W1_OFF + (uint32_t)(u - U0) * 16384, bst,
                          acc1, lane, warpM, warpN);
        }
    }
    __syncthreads();
}

#define ZACC(a) do { \
_Pragma("unroll") for (int _i = 0; _i < 2; _i++) \
_Pragma("unroll") for (int _j = 0; _j < 2; _j++) \
_Pragma("unroll") for (int _k = 0; _k < 4; _k++) (a)[_i][_j][_k] = 0.f; } while (0)

// ---------------- pointwise (one layer, one cell per thread) ----------------
__device__ __forceinline__ void pw_layer(const float* __restrict__ part,
    const float* __restrict__ bias, const float* __restrict__ Wc,
    float* __restrict__ cb, h16* __restrict__ h_buf,
    float* __restrict__ out, int t, bool isL1, int cell)
{
    int b = cell >> 10, j = cell & (HH - 1);
    float si = 0.f, sg = 0.f, so = 0.f;
#pragma unroll
    for (int sp = 0; sp < SPLITS; sp++) {
        const float* p = part + ((size_t)sp * NB + b) * G3 + j;
        si += p[0]; sg += p[HH]; so += p[2 * HH];
    }
    float pi = si + bias[j];
    float pg = sg + bias[2 * HH + j];
    float po = so + bias[3 * HH + j];
    float c = cb[cell];
    float ig = sigmoid_(pi + Wc[j] * c);
    float gg = tanh_(pg);
    float og = sigmoid_(po + Wc[2 * HH + j] * c);
    float cn = gg * (c + ig);      // faithful: forget gate unused
    float hn = og * tanh_(c);      // faithful: uses OLD cell state
    cb[cell] = cn;
    h_buf[cell] = __float2half(hn);
    if (isL1) {
        out[((size_t)b * TT + t) * HH + j] = hn;
        if (t == TT - 1) {
            out[(size_t)NB * TT * HH + cell] = hn;
            out[(size_t)NB * TT * HH + NB * HH + cell] = cn;
        }
    }
}

__global__ __launch_bounds__(NTHREADS, 1) void lstm_persistent(
    const float* __restrict__ b0, const float* __restrict__ b1,
    const float* __restrict__ Wc0, const float* __restrict__ Wc1,
    float* __restrict__ out)
{
    extern __shared__ char smem_raw[];
    uint32_t smem = smem_u32(smem_raw);
    const int ct = blockIdx.x / SPLITS, sp = blockIdx.x % SPLITS;
    const int col0 = ct * 128;
    const int lo1 = (sp * CH1) / SPLITS, hi1 = ((sp + 1) * CH1) / SPLITS;
    const int n1 = hi1 - lo1;
    const int nx = (sp < 2) ? 2 : 1;           // static x slots in gemm0 round-robin
    const int tid = threadIdx.x;
    const int cell = blockIdx.x * NTHREADS + tid;
    const bool hasCell = (cell < NB * HH);

    // one-time: resident W slices (gemm0 slots round-robin: chunk sp + 6*s)
#pragma unroll
    for (int s = 0; s < 4; s++)
        load_Wslot(smem + W0_OFF + s * 16384, g_W0 + (size_t)col0 * K0,
                   (sp + SPLITS * s) * 64, K0, tid);
    for (int s = 0; s < n1; s++)
        load_Wslot(smem + W1_OFF + s * 16384, g_W1 + (size_t)col0 * K1,
                   (lo1 + s) * 64, K1, tid);
    CP_COMMIT();
    asm volatile("cp.async.wait_group 0;" ::: "memory");
    __syncthreads();

    int sense = 0, as = 0, ws = 0;
    // ---- prologue: h0(0) (h0/h1 initial zeros already global-visible)
    {
        float acc[2][2][4]; ZACC(acc);
        gemm_chunks<0>(smem, acc, 0, 4, sp, 0);
        store_part(acc, g_part0, sp, col0);
        grid_sync(sense);
        if (hasCell) pw_layer(g_part0, b0, Wc0, g_c0, g_h0, out, 0, false, cell);
        dbar_arrive(as);
    }

    // ---- steady state: 1 blocking sync + 1 hidden (deferred) sync per step
    for (int t = 0; t < TT; t++) {
        const int U0 = (t + 1 < TT) ? (4 - nx) : 0;
        float acc0[2][2][4];
        if (t + 1 < TT) {                     // gemm0(t+1): x-chunks BEFORE the wait
            ZACC(acc0);
            gemm_chunks<0>(smem, acc0, 0, nx, sp, t + 1);
        }
        dbar_wait(ws);                        // pw(t-1 epoch) globally complete
        {
            float acc1[2][2][4]; ZACC(acc1);
            gemm_fused(smem, acc0, acc1, sp, col0, t, nx, U0, n1);
            store_part(acc1, g_part1, sp, col0);
        }
        grid_sync(sense);                     // all partials visible
        if (hasCell) {
            pw_layer(g_part1, b1, Wc1, g_c1, g_h1, out, t, true, cell);
            if (t + 1 < TT)
                pw_layer(g_part0, b0, Wc0, g_c0, g_h0, out, t + 1, false, cell);
        }
        dbar_arrive(as);
    }
}

// ---------------- host launch ----------------
extern "C" void kernel_launch(void* const* d_in, const int* in_sizes, int n_in,
                              void* d_out, int out_size) {
    const float* x   = (const float*)d_in[0];
    const float* Wx0 = (const float*)d_in[1];
    const float* Wh0 = (const float*)d_in[2];
    const float* b0  = (const float*)d_in[3];
    const float* Wc0 = (const float*)d_in[4];
    const float* Wx1 = (const float*)d_in[5];
    const float* Wh1 = (const float*)d_in[6];
    const float* b1  = (const float*)d_in[7];
    const float* Wc1 = (const float*)d_in[8];
    float* out = (float*)d_out;

    cudaFuncSetAttribute(lstm_persistent,
                         cudaFuncAttributeMaxDynamicSharedMemorySize, SMEM_TOTAL);

    size_t total_conv = NW0E + NW1E + NXE;
    int conv_blocks = (int)((total_conv + 255) / 256);

    init_state<<<256, 256>>>();
    convert_all<<<conv_blocks, 256>>>(x, Wx0, Wh0, Wx1, Wh1);
    lstm_persistent<<<GRID, NTHREADS, SMEM_TOTAL>>>(b0, b1, Wc0, Wc1, out);
}